// round 8
// baseline (speedup 1.0000x reference)
#include <cuda_runtime.h>

// APMLSparse: x[B,N,3], y[B,M,3] fp32 -> scalar loss. B=4, N=M=4096.
// Per row: d_j = sqrt(max(||x-y_j||^2,1e-12)), e_j=exp(-d_j), Z=sum e_j.
// Kept = d-ascending prefix while exclusive cumulative mass < 0.8*Z (incl.
// crossing entry, p>1e-10 filter). loss += sum_kept e_j*d_j / Z.
//
// R6: two-stage private banked histogram (16 bins x 512 columns, zero
// atomics), d stored in smem (not regs) to cut registers to ~42 and fit
// 3 CTAs/SM (48 warps). Read-and-clear bin reduce; stage-2 fuses the
// below-bin kept accumulation; final ~140-element band solved directly by
// exact O(k^2) rank resolution. Scalar FFMA math.

#define NTH  512
#define NPT  8              // 4096 / NTH
#define RPC  8
#define MPTS 4096
#define NB   16
#define CAP  320
#define HIST_BYTES (NB * NTH * 4)   // 32768

__global__ void apml_zero_out(float* o) { o[0] = 0.0f; }

__global__ __launch_bounds__(NTH, 3)
void apml_kernel(const float* __restrict__ x, const float* __restrict__ y,
                 float* __restrict__ out)
{
    extern __shared__ float hist[];     // NB*NTH floats (32 KB dynamic)
    __shared__ float  dArr[MPTS];       // 16 KB: d per element of this row
    __shared__ float2 list[CAP];        // 2.5 KB
    __shared__ float  binTot[NB];
    __shared__ float  warpRed[16];
    __shared__ float  s_ctl[8];         // 0:Z 1:T 2:c1 3:mLo1 4:c2 5:mLo2 6:rcpZ
    __shared__ int    s_cnt;

    const int tid = threadIdx.x, lane = tid & 31, wid = tid >> 5;
    const int cpb = MPTS / RPC;                    // 512
    const int b = blockIdx.x / cpb;
    const int rowBase = (blockIdx.x % cpb) * RPC;

    // 8 y-points per thread in registers, reused across RPC rows.
    float yx[NPT], yy[NPT], yz[NPT];
    const float* yb = y + (size_t)b * MPTS * 3;
#pragma unroll
    for (int k = 0; k < NPT; k++) {
        int j = k * NTH + tid;
        yx[k] = yb[j * 3 + 0];
        yy[k] = yb[j * 3 + 1];
        yz[k] = yb[j * 3 + 2];
    }

    // Initial histogram zero (read-and-clear reduces keep it clean after).
    float4* h4 = (float4*)hist;
#pragma unroll
    for (int i = 0; i < NB * NTH / 4 / NTH; i++)
        h4[tid + i * NTH] = make_float4(0.f, 0.f, 0.f, 0.f);

    float ctaAcc = 0.0f;
    __syncthreads();

    for (int r = 0; r < RPC; r++) {
        const float* xp = x + ((size_t)b * MPTS + rowBase + r) * 3;
        const float x0 = __ldg(xp + 0);
        const float x1 = __ldg(xp + 1);
        const float x2 = __ldg(xp + 2);

        // ---- pass 1: d -> smem, exp-mass into stage-1 bins (width 1) ----
#pragma unroll
        for (int k = 0; k < NPT; k++) {
            float dx = x0 - yx[k];
            float dy = x1 - yy[k];
            float dz = x2 - yz[k];
            float sq = fmaf(dx, dx, fmaf(dy, dy, dz * dz));
            sq = fmaxf(sq, 1e-12f);
            float d = sq * rsqrtf(sq);               // sqrt via MUFU.RSQ + FMUL
            dArr[k * NTH + tid] = d;
            float ex = __expf(-d);
            int bin = (int)d;
            bin = bin < (NB - 1) ? bin : (NB - 1);
            hist[bin * NTH + tid] += ex;             // conflict-free column
        }
        __syncthreads();

        // ---- reduce stage-1 bins and zero them: warp w -> bin w ----
        {
            float4* col = (float4*)(hist + wid * NTH);
            float s = 0.f;
#pragma unroll
            for (int i = 0; i < NTH / 4 / 32; i++) {
                float4 v = col[lane + 32 * i];
                s += (v.x + v.y) + (v.z + v.w);
                col[lane + 32 * i] = make_float4(0.f, 0.f, 0.f, 0.f);
            }
#pragma unroll
            for (int o = 16; o; o >>= 1) s += __shfl_xor_sync(0xffffffffu, s, o);
            if (lane == 0) binTot[wid] = s;
        }
        __syncthreads();

        // ---- scan stage 1 (warp 0; 16 live lanes) ----
        if (wid == 0) {
            float mm = (lane < NB) ? binTot[lane] : 0.f;
            float incl = mm;
#pragma unroll
            for (int o = 1; o < 32; o <<= 1) {
                float t = __shfl_up_sync(0xffffffffu, incl, o);
                if (lane >= o) incl += t;
            }
            float total = __shfl_sync(0xffffffffu, incl, 31);
            float T = 0.8f * total;
            float excl = incl - mm;
            unsigned bal = __ballot_sync(0xffffffffu,
                                         (lane < NB) && (excl < T) && (incl >= T));
            int c1 = bal ? (__ffs(bal) - 1) : (NB - 1);
            float mlo = __shfl_sync(0xffffffffu, excl, c1);
            if (lane == 0) {
                s_ctl[0] = total;
                s_ctl[1] = T;
                s_ctl[2] = __int_as_float(c1);
                s_ctl[3] = mlo;
                s_ctl[6] = __frcp_rn(total);
                s_cnt = 0;    // safe here: all prior-row list/s_cnt reads are
            }                 // ordered before this by the pass-1 barrier
        }
        __syncthreads();
        const float Z    = s_ctl[0];
        const float T    = s_ctl[1];
        const int   c1s  = __float_as_int(s_ctl[2]) << 4;   // c1*16
        const float mLo1 = s_ctl[3];
        const float rcpZ = s_ctl[6];

        // ---- stage-2 fill (16 sub-bins, width 1/16) + below-bin kept accum ----
        float acc = 0.0f;
#pragma unroll
        for (int k = 0; k < NPT; k++) {
            float d = dArr[k * NTH + tid];
            int b2 = (int)(16.0f * d) - c1s;   // exact: x16 scaling is a 2^4 shift
            if (b2 < 0) {
                acc = fmaf(__expf(-d), d, acc);
            } else if (b2 < NB) {
                hist[b2 * NTH + tid] += __expf(-d);
            }
        }
        __syncthreads();

        // ---- reduce stage-2 bins and zero them ----
        {
            float4* col = (float4*)(hist + wid * NTH);
            float s = 0.f;
#pragma unroll
            for (int i = 0; i < NTH / 4 / 32; i++) {
                float4 v = col[lane + 32 * i];
                s += (v.x + v.y) + (v.z + v.w);
                col[lane + 32 * i] = make_float4(0.f, 0.f, 0.f, 0.f);
            }
#pragma unroll
            for (int o = 16; o; o >>= 1) s += __shfl_xor_sync(0xffffffffu, s, o);
            if (lane == 0) binTot[wid] = s;
        }
        __syncthreads();

        // ---- scan stage 2 ----
        if (wid == 0) {
            float mm = (lane < NB) ? binTot[lane] : 0.f;
            float incl = mm;
#pragma unroll
            for (int o = 1; o < 32; o <<= 1) {
                float t = __shfl_up_sync(0xffffffffu, incl, o);
                if (lane >= o) incl += t;
            }
            float excl = incl - mm;
            unsigned bal = __ballot_sync(0xffffffffu,
                (lane < NB) && (mLo1 + excl < T) && (mLo1 + incl >= T));
            int c2 = bal ? (__ffs(bal) - 1) : (NB - 1);   // fp-mismatch fallback
            float mlo2 = mLo1 + __shfl_sync(0xffffffffu, excl, c2);
            if (lane == 0) {
                s_ctl[4] = __int_as_float(c2);
                s_ctl[5] = mlo2;
            }
        }
        __syncthreads();
        const int   ce   = c1s + __float_as_int(s_ctl[4]);  // crossing sub-bin id
        const float mLo2 = s_ctl[5];

        // ---- compact: sub-bins [c1s,ce) kept; sub-bin ce -> band list ----
#pragma unroll
        for (int k = 0; k < NPT; k++) {
            float d = dArr[k * NTH + tid];
            int b2 = (int)(16.0f * d);
            bool kept = (b2 >= c1s) && (b2 < ce);
            bool band = (b2 == ce);
            if (kept) acc = fmaf(__expf(-d), d, acc);
            unsigned mk = __ballot_sync(0xffffffffu, band);
            if (mk) {
                int leader = __ffs(mk) - 1;
                int base = 0;
                if (lane == leader) base = atomicAdd(&s_cnt, __popc(mk));
                base = __shfl_sync(0xffffffffu, base, leader);
                if (band) {
                    int idx = base + __popc(mk & ((1u << lane) - 1u));
                    float ex = __expf(-d);
                    if (idx < CAP) list[idx] = make_float2(d, ex);
                    else           acc = fmaf(ex, d, acc);   // overflow fallback
                }
            }
        }
        __syncthreads();

        // ---- exact O(k^2) rank resolution on the ~140-element band ----
        const int   cnt  = s_cnt < CAP ? s_cnt : CAP;
        const float Trem = T - mLo2;
        const float eThr = 1e-10f * Z;
        for (int i = tid; i < cnt; i += NTH) {
            float2 vi = list[i];
            float rm = 0.f;
            for (int j = 0; j < cnt; j++) {
                float2 vj = list[j];
                rm += ((vj.x < vi.x) || (vj.x == vi.x && j < i)) ? vj.y : 0.f;
            }
            if (rm < Trem && vi.y > eThr) acc = fmaf(vi.y, vi.x, acc);
        }

        // ---- fold row into per-thread accumulator ----
        ctaAcc = fmaf(acc, rcpZ, ctaAcc);
        // next row's pass-1 barrier orders everything; s_cnt reset happens
        // inside the scan-1 critical section (after that barrier).
    }

    // ---- one block reduce per CTA ----
#pragma unroll
    for (int o = 16; o; o >>= 1) ctaAcc += __shfl_xor_sync(0xffffffffu, ctaAcc, o);
    if (lane == 0) warpRed[wid] = ctaAcc;
    __syncthreads();
    if (tid == 0) {
        float tot = 0.f;
#pragma unroll
        for (int i = 0; i < 16; i++) tot += warpRed[i];
        atomicAdd(out, tot);
    }
}

extern "C" void kernel_launch(void* const* d_in, const int* in_sizes, int n_in,
                              void* d_out, int out_size)
{
    const float* x = (const float*)d_in[0];
    const float* y = (const float*)d_in[1];
    float* out = (float*)d_out;

    cudaFuncSetAttribute(apml_kernel,
                         cudaFuncAttributeMaxDynamicSharedMemorySize, HIST_BYTES);

    apml_zero_out<<<1, 1>>>(out);
    const int grid = (4 * MPTS) / RPC;   // 2048 CTAs
    apml_kernel<<<grid, NTH, HIST_BYTES>>>(x, y, out);
}